// round 15
// baseline (speedup 1.0000x reference)
#include <cuda_runtime.h>
#include <cstdint>

// Problem constants
// x: [B=2, E=512, S=128, L=128] fp32 ; W: [1536, 512] ; b: [1536]
// out: [2, 512, 128, 128] fp32
#define NB 2
#define NH 8
#define DH 64
#define NS 128
#define NL 128
#define QKV_ELEMS (NB * NH * NS * NL * DH)   // 16,777,216 floats = 64MB

__device__ __align__(256) float g_q[QKV_ELEMS];
__device__ __align__(256) float g_k[QKV_ELEMS];
__device__ __align__(256) float g_v[QKV_ELEMS];
__device__ __align__(256) float g_oc[QKV_ELEMS];
__device__ __align__(256) float g_xr[NB * 16384 * 512];   // X transposed [b][p][i], tf32-rounded
__device__ __align__(256) float g_wr[1536 * 512];         // tf32-rounded W

// ---------- helpers ----------
__device__ __forceinline__ uint32_t tf32u(float x) {
    uint32_t r;
    asm("cvt.rna.tf32.f32 %0, %1;" : "=r"(r) : "f"(x));
    return r;
}
__device__ __forceinline__ float tf32f(float x) { return __uint_as_float(tf32u(x)); }
__device__ __forceinline__ uint32_t fu(float x) { return __float_as_uint(x); }

__device__ __forceinline__ void mma8(float (&d)[4], const uint32_t (&a)[4], const uint32_t (&b)[2]) {
    asm volatile(
        "mma.sync.aligned.m16n8k8.row.col.f32.tf32.tf32.f32 "
        "{%0,%1,%2,%3}, {%4,%5,%6,%7}, {%8,%9}, {%0,%1,%2,%3};\n"
        : "+f"(d[0]), "+f"(d[1]), "+f"(d[2]), "+f"(d[3])
        : "r"(a[0]), "r"(a[1]), "r"(a[2]), "r"(a[3]), "r"(b[0]), "r"(b[1]));
}

// ldmatrix x4: lanes 8i..8i+7 supply the 16B-row addresses of matrix i.
__device__ __forceinline__ void ldsm4(uint32_t (&r)[4], uint32_t addr) {
    asm volatile("ldmatrix.sync.aligned.m8n8.x4.shared.b16 {%0,%1,%2,%3}, [%4];"
        : "=r"(r[0]), "=r"(r[1]), "=r"(r[2]), "=r"(r[3]) : "r"(addr));
}

__device__ __forceinline__ uint32_t smem_u32(const void* p) {
    uint32_t a;
    asm("{ .reg .u64 t; cvta.to.shared.u64 t, %1; cvt.u32.u64 %0, t; }" : "=r"(a) : "l"(p));
    return a;
}
__device__ __forceinline__ void cpa16(uint32_t dst, const void* src) {
    asm volatile("cp.async.cg.shared.global [%0], [%1], 16;" :: "r"(dst), "l"(src) : "memory");
}
#define CP_COMMIT() asm volatile("cp.async.commit_group;" ::: "memory")
#define CP_WAIT(n)  asm volatile("cp.async.wait_group %0;" :: "n"(n) : "memory")

// =====================================================================
// K0a: transpose X [b][i][p] -> g_xr [b][p][i], tf32-rounded. occ 3.
// =====================================================================
#define XT_SMEM (128 * 129 * 4)
__global__ void __launch_bounds__(256, 3) k_xt(const float* __restrict__ X) {
    extern __shared__ float sm[];
    float* t = sm;
    const int tid = threadIdx.x;
    const int p0 = blockIdx.x * 128, i0 = blockIdx.y * 128, b = blockIdx.z;
    const float* src = X + ((size_t)(b * 512 + i0)) * 16384 + p0;
#pragma unroll
    for (int it = 0; it < 16; it++) {
        int idx = it * 256 + tid;
        int i = idx >> 5, p4 = (idx & 31) * 4;
        float4 v = *reinterpret_cast<const float4*>(src + (size_t)i * 16384 + p4);
        t[i * 129 + p4 + 0] = tf32f(v.x);
        t[i * 129 + p4 + 1] = tf32f(v.y);
        t[i * 129 + p4 + 2] = tf32f(v.z);
        t[i * 129 + p4 + 3] = tf32f(v.w);
    }
    __syncthreads();
    float* dst = g_xr + ((size_t)(b * 16384 + p0)) * 512 + i0;
#pragma unroll
    for (int it = 0; it < 16; it++) {
        int idx = it * 256 + tid;
        int p = idx >> 5, i4 = (idx & 31) * 4;
        float4 v;
        v.x = t[(i4 + 0) * 129 + p];
        v.y = t[(i4 + 1) * 129 + p];
        v.z = t[(i4 + 2) * 129 + p];
        v.w = t[(i4 + 3) * 129 + p];
        *reinterpret_cast<float4*>(dst + (size_t)p * 512 + i4) = v;
    }
}

// K0b: tf32-round a buffer (for W).
__global__ void k_round(const float* __restrict__ src, float* __restrict__ dst, int n4) {
    int i = blockIdx.x * blockDim.x + threadIdx.x;
    if (i < n4) {
        float4 v = reinterpret_cast<const float4*>(src)[i];
        reinterpret_cast<float4*>(dst)[i] = make_float4(tf32f(v.x), tf32f(v.y), tf32f(v.z), tf32f(v.w));
    }
}

// =====================================================================
// K1: QKV GEMM.  C[o, p] = sum_i Wr[o,i] * Xr[b][p,i] (+bias), p = s*128+l
// CTA tile 256(o) x 128(p), occupancy 1, 8 warps in 4m x 2n grid
// (warp tile 64 x 64, acc = 128 regs). K chunks of 32, 3-stage cp.async.
// smem: A0/A1/A2 [0,98304) ([256 rows][32 k] swizzled, 32KB each),
//       B0/B1/B2 [98304,147456) ([128 rows][32 k], 16KB each).
// Epilogue: two 128-row halves staged through Cs [128][129] overlay.
// Outputs q,k,v written tf32-ROUNDED (post bias+scale).
// =====================================================================
#define K1_SMEM 147456

__global__ void __launch_bounds__(256, 1) k_qkv(const float* __restrict__ bias) {
    extern __shared__ float sm[];
    const uint32_t sb = smem_u32(sm);
    const int tid = threadIdx.x;
    const int warp = tid >> 5, lane = tid & 31;
    const int g = lane >> 2, qc = lane & 3;
    const int sub = lane >> 3, rr = lane & 7;       // ldmatrix lane decomposition
    const int wm = warp >> 1, wn = warp & 1;        // 4 x 2 warp grid
    const int o0 = blockIdx.x * 256;
    const int s = blockIdx.y;
    const int b = blockIdx.z;
    const float* Wt = g_wr + (size_t)o0 * 512;
    const float* Bt = g_xr + ((size_t)b * 16384 + (size_t)s * 128) * 512;

    float acc[4][8][4];
#pragma unroll
    for (int i = 0; i < 4; i++)
#pragma unroll
        for (int j = 0; j < 8; j++)
#pragma unroll
            for (int k = 0; k < 4; k++) acc[i][j][k] = 0.f;

    // stage chunk c: A [256 o][32 k] and B [128 p][32 k], both swizzled
    auto stage = [&](int c, int buf) {
        const float* wa = Wt + c * 32;
#pragma unroll
        for (int it = 0; it < 8; it++) {
            int idx = it * 256 + tid;          // 0..2047
            int r = idx >> 3;                  // row 0..255
            int kq = idx & 7;                  // k quad 0..7
            uint32_t dst = sb + (uint32_t)(buf * 32768 + r * 128 + ((kq ^ (r & 7)) << 4));
            cpa16(dst, wa + (size_t)r * 512 + kq * 4);
        }
        const float* xa = Bt + c * 32;
#pragma unroll
        for (int it = 0; it < 4; it++) {
            int idx = it * 256 + tid;
            int r = idx >> 3;                  // row 0..127
            int kq = idx & 7;
            uint32_t dst = sb + (uint32_t)(98304 + buf * 16384 + r * 128 + ((kq ^ (r & 7)) << 4));
            cpa16(dst, xa + (size_t)r * 512 + kq * 4);
        }
    };

    auto compute = [&](int buf) {
        const uint32_t Ab = sb + (uint32_t)(buf * 32768);
        const uint32_t Bb = sb + (uint32_t)(98304 + buf * 16384);
#pragma unroll
        for (int s8 = 0; s8 < 4; s8++) {
            uint32_t af[4][4], bf[4][4];
#pragma unroll
            for (int mt = 0; mt < 4; mt++) {
                int row = wm * 64 + mt * 16 + ((sub & 1) << 3) + rr;
                int q = 2 * s8 + (sub >> 1);
                ldsm4(af[mt], Ab + (uint32_t)(row * 128 + ((q ^ (row & 7)) << 4)));
            }
#pragma unroll
            for (int np = 0; np < 4; np++) {
                int n = wn * 64 + np * 16 + ((sub >> 1) << 3) + rr;
                int q = 2 * s8 + (sub & 1);
                ldsm4(bf[np], Bb + (uint32_t)(n * 128 + ((q ^ (n & 7)) << 4)));
            }
#pragma unroll
            for (int mt = 0; mt < 4; mt++)
#pragma unroll
                for (int nt = 0; nt < 8; nt++) {
                    const uint32_t bb[2] = { bf[nt >> 1][(nt & 1) * 2], bf[nt >> 1][(nt & 1) * 2 + 1] };
                    mma8(acc[mt][nt], af[mt], bb);
                }
        }
    };

    stage(0, 0);
    CP_COMMIT();
    stage(1, 1);
    CP_COMMIT();
    for (int c = 0; c < 16; c++) {
        if (c < 15) { CP_WAIT(1); } else { CP_WAIT(0); }
        __syncthreads();
        compute(c % 3);
        if (c + 2 < 16) {
            stage(c + 2, (c + 2) % 3);
            CP_COMMIT();
        }
    }
    __syncthreads();

    // Epilogue in two 128-row halves through Cs [128][129]
    float* Cs = sm;
#pragma unroll
    for (int half = 0; half < 2; half++) {
        if ((wm >> 1) == half) {       // warps owning rows in this half
#pragma unroll
            for (int mt = 0; mt < 4; mt++)
#pragma unroll
                for (int nt = 0; nt < 8; nt++) {
                    int r = (wm * 64 + mt * 16 + g) & 127;
                    int n = wn * 64 + nt * 8 + 2 * qc;
                    Cs[r * 129 + n] = acc[mt][nt][0];
                    Cs[r * 129 + n + 1] = acc[mt][nt][1];
                    Cs[(r + 8) * 129 + n] = acc[mt][nt][2];
                    Cs[(r + 8) * 129 + n + 1] = acc[mt][nt][3];
                }
        }
        __syncthreads();

        const int o0h = o0 + half * 128;
        const int sel = o0h >> 9;                // 0=q 1=k 2=v
        const int h0 = (o0h & 511) >> 6;
        float* dst = (sel == 0) ? g_q : ((sel == 1) ? g_k : g_v);
        const float scale = (sel == 0) ? 0.125f : 1.0f;
#pragma unroll
        for (int rep = 0; rep < 16; rep++) {
            int idx = rep * 256 + tid;
            int d4 = (idx & 15) * 4;
            int l = (idx >> 4) & 127;
            int hh = idx >> 11;
            int od = hh * 64 + d4;
            float4 v;
            v.x = tf32f((Cs[(od + 0) * 129 + l] + bias[o0h + od + 0]) * scale);
            v.y = tf32f((Cs[(od + 1) * 129 + l] + bias[o0h + od + 1]) * scale);
            v.z = tf32f((Cs[(od + 2) * 129 + l] + bias[o0h + od + 2]) * scale);
            v.w = tf32f((Cs[(od + 3) * 129 + l] + bias[o0h + od + 3]) * scale);
            size_t da = (((size_t)((b * 8 + h0 + hh) * 128 + s)) * 128 + l) * 64 + d4;
            *reinterpret_cast<float4*>(dst + da) = v;
        }
        __syncthreads();
    }
}

// =====================================================================
// Attention core: 128 x 128 x 64 per CTA, 8 warps, 2 CTA/SM.
// Q+K in cp.async group 0, V in group 1 (QK starts before V lands).
// QK: warp = 16 rows (shuffle softmax), frags via ldmatrix.
// PV: warp grid 4m x 2n; col writes STG direct from accumulators.
// smem: Qs[128][68] | Ks[128][68] | Vs[128][68]; Ps[128][132] overlays Qs+Ks.
// =====================================================================
#define ATTN_SMEM (3 * 128 * 68 * 4)   // 104,448 B
#define QS_OFF 0
#define KS_OFF (128 * 68 * 4)
#define VS_OFF (2 * 128 * 68 * 4)

// K2: column attention. Block = (l, h, b). Writes g_oc[b][h][s][l][d].
__global__ void __launch_bounds__(256, 2) k_colattn() {
    extern __shared__ float sm[];
    const uint32_t sb = smem_u32(sm);
    float* Vs = sm + 2 * 128 * 68;
    float* Ps = sm;                   // [128][132] overlay on Qs+Ks
    const int tid = threadIdx.x;
    const int warp = tid >> 5, lane = tid & 31;
    const int g = lane >> 2, qc = lane & 3;
    const int sub = lane >> 3, rr = lane & 7;
    const int l = blockIdx.x, h = blockIdx.y, b = blockIdx.z;
    const size_t base = (size_t)((b * 8 + h) * 128) * 8192;

    // group 0: Q + K; group 1: V
#pragma unroll
    for (int rep = 0; rep < 8; rep++) {
        int idx = rep * 256 + tid;
        int s = idx >> 4;
        int d4 = (idx & 15) * 4;
        size_t ga = base + (size_t)s * 8192 + (size_t)l * 64 + d4;
        uint32_t so = (uint32_t)(s * 68 + d4) * 4;
        cpa16(sb + QS_OFF + so, g_q + ga);
        cpa16(sb + KS_OFF + so, g_k + ga);
    }
    CP_COMMIT();
#pragma unroll
    for (int rep = 0; rep < 8; rep++) {
        int idx = rep * 256 + tid;
        int s = idx >> 4;
        int d4 = (idx & 15) * 4;
        size_t ga = base + (size_t)s * 8192 + (size_t)l * 64 + d4;
        cpa16(sb + VS_OFF + (uint32_t)(s * 68 + d4) * 4, g_v + ga);
    }
    CP_COMMIT();
    CP_WAIT(1);            // Q,K ready; V still in flight
    __syncthreads();

    // ---- QK: scores[s][t], warp owns rows 16w..16w+15 ----
    float sc[16][4];
#pragma unroll
    for (int nt = 0; nt < 16; nt++)
#pragma unroll
        for (int k = 0; k < 4; k++) sc[nt][k] = 0.f;
    const int row = warp * 16;
#pragma unroll
    for (int k0 = 0; k0 < 64; k0 += 8) {
        uint32_t a[4];
        {
            int rq = row + ((sub & 1) << 3) + rr;
            ldsm4(a, sb + QS_OFF + (uint32_t)(rq * 68 + k0 + ((sub >> 1) << 2)) * 4);
        }
#pragma unroll
        for (int np = 0; np < 8; np++) {
            uint32_t bf[4];
            int n = np * 16 + ((sub >> 1) << 3) + rr;
            ldsm4(bf, sb + KS_OFF + (uint32_t)(n * 68 + k0 + ((sub & 1) << 2)) * 4);
            const uint32_t b0[2] = { bf[0], bf[1] };
            const uint32_t b1[2] = { bf[2], bf[3] };
            mma8(sc[np * 2], a, b0);
            mma8(sc[np * 2 + 1], a, b1);
        }
    }
    // ---- softmax over t ----
    float m0 = -1e30f, m1 = -1e30f;
#pragma unroll
    for (int nt = 0; nt < 16; nt++) {
        m0 = fmaxf(m0, fmaxf(sc[nt][0], sc[nt][1]));
        m1 = fmaxf(m1, fmaxf(sc[nt][2], sc[nt][3]));
    }
    m0 = fmaxf(m0, __shfl_xor_sync(0xffffffffu, m0, 1));
    m0 = fmaxf(m0, __shfl_xor_sync(0xffffffffu, m0, 2));
    m1 = fmaxf(m1, __shfl_xor_sync(0xffffffffu, m1, 1));
    m1 = fmaxf(m1, __shfl_xor_sync(0xffffffffu, m1, 2));
    const float LOG2E = 1.4426950408889634f;
    float s0 = 0.f, s1 = 0.f;
#pragma unroll
    for (int nt = 0; nt < 16; nt++) {
        sc[nt][0] = exp2f((sc[nt][0] - m0) * LOG2E); s0 += sc[nt][0];
        sc[nt][1] = exp2f((sc[nt][1] - m0) * LOG2E); s0 += sc[nt][1];
        sc[nt][2] = exp2f((sc[nt][2] - m1) * LOG2E); s1 += sc[nt][2];
        sc[nt][3] = exp2f((sc[nt][3] - m1) * LOG2E); s1 += sc[nt][3];
    }
    s0 += __shfl_xor_sync(0xffffffffu, s0, 1);
    s0 += __shfl_xor_sync(0xffffffffu, s0, 2);
    s1 += __shfl_xor_sync(0xffffffffu, s1, 1);
    s1 += __shfl_xor_sync(0xffffffffu, s1, 2);
    const float inv0 = 1.0f / s0, inv1 = 1.0f / s1;

    __syncthreads();                         // Qs/Ks dead; Ps may overwrite
#pragma unroll
    for (int nt = 0; nt < 16; nt++) {
        int n = nt * 8 + 2 * qc;
        Ps[(row + g) * 132 + n] = tf32f(sc[nt][0] * inv0);
        Ps[(row + g) * 132 + n + 1] = tf32f(sc[nt][1] * inv0);
        Ps[(row + g + 8) * 132 + n] = tf32f(sc[nt][2] * inv1);
        Ps[(row + g + 8) * 132 + n + 1] = tf32f(sc[nt][3] * inv1);
    }
    CP_WAIT(0);                              // V landed long ago
    __syncthreads();

    // ---- PV: warp grid 4m x 2n ----
    const int wm2 = warp >> 1, wn2 = warp & 1;
    float oa[2][4][4];
#pragma unroll
    for (int mt = 0; mt < 2; mt++)
#pragma unroll
        for (int j = 0; j < 4; j++)
#pragma unroll
            for (int k = 0; k < 4; k++) oa[mt][j][k] = 0.f;
#pragma unroll
    for (int k0 = 0; k0 < 128; k0 += 8) {
        uint32_t a[2][4];
#pragma unroll
        for (int mt = 0; mt < 2; mt++) {
            int rp = wm2 * 32 + mt * 16 + ((sub & 1) << 3) + rr;
            ldsm4(a[mt], sb + QS_OFF + (uint32_t)(rp * 132 + k0 + ((sub >> 1) << 2)) * 4);
        }
#pragma unroll
        for (int j = 0; j < 4; j++) {
            uint32_t bb[2];
            int n = (wn2 * 4 + j) * 8 + g;
            bb[0] = fu(Vs[(k0 + qc) * 68 + n]);
            bb[1] = fu(Vs[(k0 + qc + 4) * 68 + n]);
#pragma unroll
            for (int mt = 0; mt < 2; mt++) mma8(oa[mt][j], a[mt], bb);
        }
    }
    // direct STG from accumulators: rows = s, cols = d
#pragma unroll
    for (int mt = 0; mt < 2; mt++)
#pragma unroll
        for (int j = 0; j < 4; j++) {
            int r2 = wm2 * 32 + mt * 16 + g;
            int n = (wn2 * 4 + j) * 8 + 2 * qc;
            float2 v0 = make_float2(oa[mt][j][0], oa[mt][j][1]);
            float2 v1 = make_float2(oa[mt][j][2], oa[mt][j][3]);
            *reinterpret_cast<float2*>(g_oc + base + (size_t)r2 * 8192 + (size_t)l * 64 + n) = v0;
            *reinterpret_cast<float2*>(g_oc + base + (size_t)(r2 + 8) * 8192 + (size_t)l * 64 + n) = v1;
        }
}

// K3: row attention + add col result + write final output [B,512,S,L].
__global__ void __launch_bounds__(256, 2) k_rowattn(float* __restrict__ out) {
    extern __shared__ float sm[];
    const uint32_t sb = smem_u32(sm);
    float* Vs = sm + 2 * 128 * 68;
    float* Ps = sm;                  // [128][132] overlay on Qs+Ks
    float* Os = sm;                  // [128][65] overlay
    const int tid = threadIdx.x;
    const int warp = tid >> 5, lane = tid & 31;
    const int g = lane >> 2, qc = lane & 3;
    const int sub = lane >> 3, rr = lane & 7;
    const int s = blockIdx.x, h = blockIdx.y, b = blockIdx.z;
    const size_t rbase = (size_t)((b * 8 + h) * 128) * 8192 + (size_t)s * 8192;

#pragma unroll
    for (int rep = 0; rep < 8; rep++) {
        int idx = rep * 256 + tid;
        int l = idx >> 4;
        int d4 = (idx & 15) * 4;
        size_t ga = rbase + (size_t)idx * 4;
        uint32_t so = (uint32_t)(l * 68 + d4) * 4;
        cpa16(sb + QS_OFF + so, g_q + ga);
        cpa16(sb + KS_OFF + so, g_k + ga);
    }
    CP_COMMIT();
#pragma unroll
    for (int rep = 0; rep < 8; rep++) {
        int idx = rep * 256 + tid;
        int l = idx >> 4;
        int d4 = (idx & 15) * 4;
        cpa16(sb + VS_OFF + (uint32_t)(l * 68 + d4) * 4, g_v + rbase + (size_t)idx * 4);
    }
    CP_COMMIT();
    CP_WAIT(1);
    __syncthreads();

    float sc[16][4];
#pragma unroll
    for (int nt = 0; nt < 16; nt++)
#pragma unroll
        for (int k = 0; k < 4; k++) sc[nt][k] = 0.f;
    const int row = warp * 16;
#pragma unroll
    for (int k0 = 0; k0 < 64; k0 += 8) {
        uint32_t a[4];
        {
            int rq = row + ((sub & 1) << 3) + rr;
            ldsm4(a, sb + QS_OFF + (uint32_t)(rq * 68 + k0 + ((sub >> 1) << 2)) * 4);
        }
#pragma unroll
        for (int np = 0; np < 8; np++) {
            uint32_t bf[4];
            int n = np * 16 + ((sub >> 1) << 3) + rr;
            ldsm4(bf, sb + KS_OFF + (uint32_t)(n * 68 + k0 + ((sub & 1) << 2)) * 4);
            const uint32_t b0[2] = { bf[0], bf[1] };
            const uint32_t b1[2] = { bf[2], bf[3] };
            mma8(sc[np * 2], a, b0);
            mma8(sc[np * 2 + 1], a, b1);
        }
    }
    float m0 = -1e30f, m1 = -1e30f;
#pragma unroll
    for (int nt = 0; nt < 16; nt++) {
        m0 = fmaxf(m0, fmaxf(sc[nt][0], sc[nt][1]));
        m1 = fmaxf(m1, fmaxf(sc[nt][2], sc[nt][3]));
    }
    m0 = fmaxf(m0, __shfl_xor_sync(0xffffffffu, m0, 1));
    m0 = fmaxf(m0, __shfl_xor_sync(0xffffffffu, m0, 2));
    m1 = fmaxf(m1, __shfl_xor_sync(0xffffffffu, m1, 1));
    m1 = fmaxf(m1, __shfl_xor_sync(0xffffffffu, m1, 2));
    const float LOG2E = 1.4426950408889634f;
    float s0 = 0.f, s1 = 0.f;
#pragma unroll
    for (int nt = 0; nt < 16; nt++) {
        sc[nt][0] = exp2f((sc[nt][0] - m0) * LOG2E); s0 += sc[nt][0];
        sc[nt][1] = exp2f((sc[nt][1] - m0) * LOG2E); s0 += sc[nt][1];
        sc[nt][2] = exp2f((sc[nt][2] - m1) * LOG2E); s1 += sc[nt][2];
        sc[nt][3] = exp2f((sc[nt][3] - m1) * LOG2E); s1 += sc[nt][3];
    }
    s0 += __shfl_xor_sync(0xffffffffu, s0, 1);
    s0 += __shfl_xor_sync(0xffffffffu, s0, 2);
    s1 += __shfl_xor_sync(0xffffffffu, s1, 1);
    s1 += __shfl_xor_sync(0xffffffffu, s1, 2);
    const float inv0 = 1.0f / s0, inv1 = 1.0f / s1;

    __syncthreads();
#pragma unroll
    for (int nt = 0; nt < 16; nt++) {
        int n = nt * 8 + 2 * qc;
        Ps[(row + g) * 132 + n] = tf32f(sc[nt][0] * inv0);
        Ps[(row + g) * 132 + n + 1] = tf32f(sc[nt][1] * inv0);
        Ps[(row + g + 8) * 132 + n] = tf32f(sc[nt][2] * inv1);
        Ps[(row + g + 8) * 132 + n + 1] = tf32f(sc[nt][3] * inv1);
    }
    CP_WAIT(0);
    __syncthreads();

    const int wm2 = warp >> 1, wn2 = warp & 1;
    float oa[2][4][4];
#pragma unroll
    for (int mt = 0; mt < 2; mt++)
#pragma unroll
        for (int j = 0; j < 4; j++)
#pragma unroll
            for (int k = 0; k < 4; k++) oa[mt][j][k] = 0.f;
#pragma unroll
    for (int k0 = 0; k0 < 128; k0 += 8) {
        uint32_t a[2][4];
#pragma unroll
        for (int mt = 0; mt < 2; mt++) {
            int rp = wm2 * 32 + mt * 16 + ((sub & 1) << 3) + rr;
            ldsm4(a[mt], sb + QS_OFF + (uint32_t)(rp * 132 + k0 + ((sub >> 1) << 2)) * 4);
        }
#pragma unroll
        for (int j = 0; j < 4; j++) {
            uint32_t bb[2];
            int n = (wn2 * 4 + j) * 8 + g;
            bb[0] = fu(Vs[(k0 + qc) * 68 + n]);
            bb[1] = fu(Vs[(k0 + qc + 4) * 68 + n]);
#pragma unroll
            for (int mt = 0; mt < 2; mt++) mma8(oa[mt][j], a[mt], bb);
        }
    }
    // fold col-attn result into accumulators (rows = l, cols = d)
#pragma unroll
    for (int mt = 0; mt < 2; mt++)
#pragma unroll
        for (int j = 0; j < 4; j++) {
            int lr = wm2 * 32 + mt * 16 + g;
            int n = (wn2 * 4 + j) * 8 + 2 * qc;
            float2 c0 = *reinterpret_cast<const float2*>(g_oc + rbase + (size_t)lr * 64 + n);
            float2 c1 = *reinterpret_cast<const float2*>(g_oc + rbase + (size_t)(lr + 8) * 64 + n);
            oa[mt][j][0] += c0.x;
            oa[mt][j][1] += c0.y;
            oa[mt][j][2] += c1.x;
            oa[mt][j][3] += c1.y;
        }
    __syncthreads();                 // all warps done reading Ps before Os overlay
#pragma unroll
    for (int mt = 0; mt < 2; mt++)
#pragma unroll
        for (int j = 0; j < 4; j++) {
            int r2 = wm2 * 32 + mt * 16 + g;
            int n = (wn2 * 4 + j) * 8 + 2 * qc;
            Os[r2 * 65 + n] = oa[mt][j][0];
            Os[r2 * 65 + n + 1] = oa[mt][j][1];
            Os[(r2 + 8) * 65 + n] = oa[mt][j][2];
            Os[(r2 + 8) * 65 + n + 1] = oa[mt][j][3];
        }
    __syncthreads();
    // transposed, fully coalesced final write: out[b][h*64+d][s][l]
#pragma unroll
    for (int rep = 0; rep < 8; rep++) {
        int idx = rep * 256 + tid;
        int d = idx >> 5;
        int l4 = (idx & 31) * 4;
        float4 v;
        v.x = Os[(l4 + 0) * 65 + d];
        v.y = Os[(l4 + 1) * 65 + d];
        v.z = Os[(l4 + 2) * 65 + d];
        v.w = Os[(l4 + 3) * 65 + d];
        size_t oaddr = (((size_t)(b * 512 + h * 64 + d)) * 128 + s) * 128 + l4;
        *reinterpret_cast<float4*>(out + oaddr) = v;
    }
}

extern "C" void kernel_launch(void* const* d_in, const int* in_sizes, int n_in,
                              void* d_out, int out_size) {
    const float* x = (const float*)d_in[0];
    const float* W = (const float*)d_in[1];
    const float* bias = (const float*)d_in[2];
    float* out = (float*)d_out;

    cudaFuncSetAttribute(k_xt, cudaFuncAttributeMaxDynamicSharedMemorySize, XT_SMEM);
    cudaFuncSetAttribute(k_qkv, cudaFuncAttributeMaxDynamicSharedMemorySize, K1_SMEM);
    cudaFuncSetAttribute(k_colattn, cudaFuncAttributeMaxDynamicSharedMemorySize, ATTN_SMEM);
    cudaFuncSetAttribute(k_rowattn, cudaFuncAttributeMaxDynamicSharedMemorySize, ATTN_SMEM);

    // X: transpose + round; W: round
    k_xt<<<dim3(128, 4, 2), 256, XT_SMEM>>>(x);
    {
        float* wr;  cudaGetSymbolAddress((void**)&wr, g_wr);
        int nw4 = 1536 * 512 / 4;            // 196,608
        k_round<<<(nw4 + 255) / 256, 256>>>(W, wr, nw4);
    }

    k_qkv<<<dim3(6, 128, 2), 256, K1_SMEM>>>(bias);
    k_colattn<<<dim3(128, 8, 2), 256, ATTN_SMEM>>>();
    k_rowattn<<<dim3(128, 8, 2), 256, ATTN_SMEM>>>(out);
}

// round 16
// speedup vs baseline: 1.0060x; 1.0060x over previous
#include <cuda_runtime.h>
#include <cstdint>

// Problem constants
// x: [B=2, E=512, S=128, L=128] fp32 ; W: [1536, 512] ; b: [1536]
// out: [2, 512, 128, 128] fp32
#define NB 2
#define NH 8
#define DH 64
#define NS 128
#define NL 128
#define QKV_ELEMS (NB * NH * NS * NL * DH)   // 16,777,216 floats = 64MB

__device__ __align__(256) float g_q[QKV_ELEMS];
__device__ __align__(256) float g_k[QKV_ELEMS];
__device__ __align__(256) float g_v[QKV_ELEMS];
__device__ __align__(256) float g_oc[QKV_ELEMS];
__device__ __align__(256) float g_xr[NB * 16384 * 512];   // X transposed [b][p][i], tf32-rounded
__device__ __align__(256) float g_wr[1536 * 512];         // tf32-rounded W

// ---------- helpers ----------
__device__ __forceinline__ uint32_t tf32u(float x) {
    uint32_t r;
    asm("cvt.rna.tf32.f32 %0, %1;" : "=r"(r) : "f"(x));
    return r;
}
__device__ __forceinline__ float tf32f(float x) { return __uint_as_float(tf32u(x)); }
__device__ __forceinline__ uint32_t fu(float x) { return __float_as_uint(x); }

__device__ __forceinline__ void mma8(float (&d)[4], const uint32_t (&a)[4], const uint32_t (&b)[2]) {
    asm volatile(
        "mma.sync.aligned.m16n8k8.row.col.f32.tf32.tf32.f32 "
        "{%0,%1,%2,%3}, {%4,%5,%6,%7}, {%8,%9}, {%0,%1,%2,%3};\n"
        : "+f"(d[0]), "+f"(d[1]), "+f"(d[2]), "+f"(d[3])
        : "r"(a[0]), "r"(a[1]), "r"(a[2]), "r"(a[3]), "r"(b[0]), "r"(b[1]));
}

// ldmatrix x4: lanes 8i..8i+7 supply the 16B-row addresses of matrix i.
__device__ __forceinline__ void ldsm4(uint32_t (&r)[4], uint32_t addr) {
    asm volatile("ldmatrix.sync.aligned.m8n8.x4.shared.b16 {%0,%1,%2,%3}, [%4];"
        : "=r"(r[0]), "=r"(r[1]), "=r"(r[2]), "=r"(r[3]) : "r"(addr));
}

__device__ __forceinline__ uint32_t smem_u32(const void* p) {
    uint32_t a;
    asm("{ .reg .u64 t; cvta.to.shared.u64 t, %1; cvt.u32.u64 %0, t; }" : "=r"(a) : "l"(p));
    return a;
}
__device__ __forceinline__ void cpa16(uint32_t dst, const void* src) {
    asm volatile("cp.async.cg.shared.global [%0], [%1], 16;" :: "r"(dst), "l"(src) : "memory");
}
#define CP_COMMIT() asm volatile("cp.async.commit_group;" ::: "memory")
#define CP_WAIT(n)  asm volatile("cp.async.wait_group %0;" :: "n"(n) : "memory")

// =====================================================================
// K0a: transpose X [b][i][p] -> g_xr [b][p][i], tf32-rounded. occ 3.
// =====================================================================
#define XT_SMEM (128 * 129 * 4)
__global__ void __launch_bounds__(256, 3) k_xt(const float* __restrict__ X) {
    extern __shared__ float sm[];
    float* t = sm;
    const int tid = threadIdx.x;
    const int p0 = blockIdx.x * 128, i0 = blockIdx.y * 128, b = blockIdx.z;
    const float* src = X + ((size_t)(b * 512 + i0)) * 16384 + p0;
#pragma unroll
    for (int it = 0; it < 16; it++) {
        int idx = it * 256 + tid;
        int i = idx >> 5, p4 = (idx & 31) * 4;
        float4 v = *reinterpret_cast<const float4*>(src + (size_t)i * 16384 + p4);
        t[i * 129 + p4 + 0] = tf32f(v.x);
        t[i * 129 + p4 + 1] = tf32f(v.y);
        t[i * 129 + p4 + 2] = tf32f(v.z);
        t[i * 129 + p4 + 3] = tf32f(v.w);
    }
    __syncthreads();
    float* dst = g_xr + ((size_t)(b * 16384 + p0)) * 512 + i0;
#pragma unroll
    for (int it = 0; it < 16; it++) {
        int idx = it * 256 + tid;
        int p = idx >> 5, i4 = (idx & 31) * 4;
        float4 v;
        v.x = t[(i4 + 0) * 129 + p];
        v.y = t[(i4 + 1) * 129 + p];
        v.z = t[(i4 + 2) * 129 + p];
        v.w = t[(i4 + 3) * 129 + p];
        *reinterpret_cast<float4*>(dst + (size_t)p * 512 + i4) = v;
    }
}

// K0b: tf32-round a buffer (for W).
__global__ void k_round(const float* __restrict__ src, float* __restrict__ dst, int n4) {
    int i = blockIdx.x * blockDim.x + threadIdx.x;
    if (i < n4) {
        float4 v = reinterpret_cast<const float4*>(src)[i];
        reinterpret_cast<float4*>(dst)[i] = make_float4(tf32f(v.x), tf32f(v.y), tf32f(v.z), tf32f(v.w));
    }
}

// =====================================================================
// K1: QKV GEMM (R14 config: 128x128 tile, occ 2, 3-stage cp.async).
// C[o, p] = sum_i Wr[o,i] * Xr[b][p,i] (+bias), p = s*128+l
// smem: A0/A1/A2 [0,49152), B0/B1/B2 [49152,98304). Cs [128][129] overlays.
// Outputs q,k,v written tf32-ROUNDED (post bias+scale).
// =====================================================================
#define K1_SMEM 98304

__global__ void __launch_bounds__(256, 2) k_qkv(const float* __restrict__ bias) {
    extern __shared__ float sm[];
    const uint32_t sb = smem_u32(sm);
    const int tid = threadIdx.x;
    const int warp = tid >> 5, lane = tid & 31;
    const int g = lane >> 2, qc = lane & 3;
    const int sub = lane >> 3, rr = lane & 7;       // ldmatrix lane decomposition
    const int wm = warp >> 2, wn = warp & 3;        // 2 x 4 warp grid
    const int o0 = blockIdx.x * 128;
    const int s = blockIdx.y;
    const int b = blockIdx.z;
    const float* Wt = g_wr + (size_t)o0 * 512;
    const float* Bt = g_xr + ((size_t)b * 16384 + (size_t)s * 128) * 512;

    float acc[4][4][4];
#pragma unroll
    for (int i = 0; i < 4; i++)
#pragma unroll
        for (int j = 0; j < 4; j++)
#pragma unroll
            for (int k = 0; k < 4; k++) acc[i][j][k] = 0.f;

    auto stage = [&](int c, int buf) {
        const float* wa = Wt + c * 32;
#pragma unroll
        for (int it = 0; it < 4; it++) {
            int idx = it * 256 + tid;
            int r = idx >> 3;
            int kq = idx & 7;
            uint32_t dst = sb + (uint32_t)(buf * 16384 + r * 128 + ((kq ^ (r & 7)) << 4));
            cpa16(dst, wa + (size_t)r * 512 + kq * 4);
        }
        const float* xa = Bt + c * 32;
#pragma unroll
        for (int it = 0; it < 4; it++) {
            int idx = it * 256 + tid;
            int r = idx >> 3;
            int kq = idx & 7;
            uint32_t dst = sb + (uint32_t)(49152 + buf * 16384 + r * 128 + ((kq ^ (r & 7)) << 4));
            cpa16(dst, xa + (size_t)r * 512 + kq * 4);
        }
    };

    auto compute = [&](int buf) {
        const uint32_t Ab = sb + (uint32_t)(buf * 16384);
        const uint32_t Bb = sb + (uint32_t)(49152 + buf * 16384);
#pragma unroll
        for (int s8 = 0; s8 < 4; s8++) {
            uint32_t af[4][4], bf[2][4];
#pragma unroll
            for (int mt = 0; mt < 4; mt++) {
                int row = wm * 64 + mt * 16 + ((sub & 1) << 3) + rr;
                int q = 2 * s8 + (sub >> 1);
                ldsm4(af[mt], Ab + (uint32_t)(row * 128 + ((q ^ (row & 7)) << 4)));
            }
#pragma unroll
            for (int np = 0; np < 2; np++) {
                int n = wn * 32 + np * 16 + ((sub >> 1) << 3) + rr;
                int q = 2 * s8 + (sub & 1);
                ldsm4(bf[np], Bb + (uint32_t)(n * 128 + ((q ^ (n & 7)) << 4)));
            }
#pragma unroll
            for (int mt = 0; mt < 4; mt++)
#pragma unroll
                for (int nt = 0; nt < 4; nt++) {
                    const uint32_t bb[2] = { bf[nt >> 1][(nt & 1) * 2], bf[nt >> 1][(nt & 1) * 2 + 1] };
                    mma8(acc[mt][nt], af[mt], bb);
                }
        }
    };

    stage(0, 0);
    CP_COMMIT();
    stage(1, 1);
    CP_COMMIT();
    for (int c = 0; c < 16; c++) {
        if (c < 15) { CP_WAIT(1); } else { CP_WAIT(0); }
        __syncthreads();
        compute(c % 3);
        if (c + 2 < 16) {
            stage(c + 2, (c + 2) % 3);
            CP_COMMIT();
        }
    }
    __syncthreads();

    float* Cs = sm;   // [128][129]
#pragma unroll
    for (int mt = 0; mt < 4; mt++)
#pragma unroll
        for (int nt = 0; nt < 4; nt++) {
            int r = wm * 64 + mt * 16 + g;
            int n = wn * 32 + nt * 8 + 2 * qc;
            Cs[r * 129 + n] = acc[mt][nt][0];
            Cs[r * 129 + n + 1] = acc[mt][nt][1];
            Cs[(r + 8) * 129 + n] = acc[mt][nt][2];
            Cs[(r + 8) * 129 + n + 1] = acc[mt][nt][3];
        }
    __syncthreads();

    const int sel = o0 >> 9;                 // 0=q 1=k 2=v
    const int h0 = (o0 & 511) >> 6;
    float* dst = (sel == 0) ? g_q : ((sel == 1) ? g_k : g_v);
    const float scale = (sel == 0) ? 0.125f : 1.0f;
#pragma unroll
    for (int rep = 0; rep < 16; rep++) {
        int idx = rep * 256 + tid;
        int d4 = (idx & 15) * 4;
        int l = (idx >> 4) & 127;
        int hh = idx >> 11;
        int od = hh * 64 + d4;
        float4 v;
        v.x = tf32f((Cs[(od + 0) * 129 + l] + bias[o0 + od + 0]) * scale);
        v.y = tf32f((Cs[(od + 1) * 129 + l] + bias[o0 + od + 1]) * scale);
        v.z = tf32f((Cs[(od + 2) * 129 + l] + bias[o0 + od + 2]) * scale);
        v.w = tf32f((Cs[(od + 3) * 129 + l] + bias[o0 + od + 3]) * scale);
        size_t da = (((size_t)((b * 8 + h0 + hh) * 128 + s)) * 128 + l) * 64 + d4;
        *reinterpret_cast<float4*>(dst + da) = v;
    }
}

// =====================================================================
// Attention core: 128 x 128 x 64 per CTA, 8 warps, 3 CTA/SM (69.6KB smem).
// bufA = Q then V; bufB = K then P (two 64-col halves) then Os (rowattn).
// QK: warp = 16 rows (shuffle softmax), frags via ldmatrix.
// PV: warp = 16 rows x 64 d, two k-passes over P halves; k order ascending
//     -> bit-identical accumulation vs single-pass.
// =====================================================================
#define ATTN_SMEM (2 * 128 * 68 * 4)   // 69,632 B
#define BUFB_OFF (128 * 68 * 4)

// K2: column attention. Block = (l, h, b). Writes g_oc[b][h][s][l][d].
__global__ void __launch_bounds__(256, 3) k_colattn() {
    extern __shared__ float sm[];
    const uint32_t sb = smem_u32(sm);
    float* Vs = sm;                   // bufA (after V load)
    float* Ps = sm + 128 * 68;        // bufB (after K dead)
    const int tid = threadIdx.x;
    const int warp = tid >> 5, lane = tid & 31;
    const int g = lane >> 2, qc = lane & 3;
    const int sub = lane >> 3, rr = lane & 7;
    const int l = blockIdx.x, h = blockIdx.y, b = blockIdx.z;
    const size_t base = (size_t)((b * 8 + h) * 128) * 8192;

    // Q -> bufA, K -> bufB
#pragma unroll
    for (int rep = 0; rep < 8; rep++) {
        int idx = rep * 256 + tid;
        int s = idx >> 4;
        int d4 = (idx & 15) * 4;
        size_t ga = base + (size_t)s * 8192 + (size_t)l * 64 + d4;
        uint32_t so = (uint32_t)(s * 68 + d4) * 4;
        cpa16(sb + so, g_q + ga);
        cpa16(sb + BUFB_OFF + so, g_k + ga);
    }
    CP_COMMIT();
    CP_WAIT(0);
    __syncthreads();

    // ---- QK: scores[s][t], warp owns rows 16w..16w+15 ----
    float sc[16][4];
#pragma unroll
    for (int nt = 0; nt < 16; nt++)
#pragma unroll
        for (int k = 0; k < 4; k++) sc[nt][k] = 0.f;
    const int row = warp * 16;
#pragma unroll
    for (int k0 = 0; k0 < 64; k0 += 8) {
        uint32_t a[4];
        {
            int rq = row + ((sub & 1) << 3) + rr;
            ldsm4(a, sb + (uint32_t)(rq * 68 + k0 + ((sub >> 1) << 2)) * 4);
        }
#pragma unroll
        for (int np = 0; np < 8; np++) {
            uint32_t bf[4];
            int n = np * 16 + ((sub >> 1) << 3) + rr;
            ldsm4(bf, sb + BUFB_OFF + (uint32_t)(n * 68 + k0 + ((sub & 1) << 2)) * 4);
            const uint32_t b0[2] = { bf[0], bf[1] };
            const uint32_t b1[2] = { bf[2], bf[3] };
            mma8(sc[np * 2], a, b0);
            mma8(sc[np * 2 + 1], a, b1);
        }
    }
    __syncthreads();                 // Q,K reads complete

    // V -> bufA (overwrites Q)
#pragma unroll
    for (int rep = 0; rep < 8; rep++) {
        int idx = rep * 256 + tid;
        int s = idx >> 4;
        int d4 = (idx & 15) * 4;
        size_t ga = base + (size_t)s * 8192 + (size_t)l * 64 + d4;
        cpa16(sb + (uint32_t)(s * 68 + d4) * 4, g_v + ga);
    }
    CP_COMMIT();

    // ---- softmax over t (registers; unchanged math) ----
    float m0 = -1e30f, m1 = -1e30f;
#pragma unroll
    for (int nt = 0; nt < 16; nt++) {
        m0 = fmaxf(m0, fmaxf(sc[nt][0], sc[nt][1]));
        m1 = fmaxf(m1, fmaxf(sc[nt][2], sc[nt][3]));
    }
    m0 = fmaxf(m0, __shfl_xor_sync(0xffffffffu, m0, 1));
    m0 = fmaxf(m0, __shfl_xor_sync(0xffffffffu, m0, 2));
    m1 = fmaxf(m1, __shfl_xor_sync(0xffffffffu, m1, 1));
    m1 = fmaxf(m1, __shfl_xor_sync(0xffffffffu, m1, 2));
    const float LOG2E = 1.4426950408889634f;
    float s0 = 0.f, s1 = 0.f;
#pragma unroll
    for (int nt = 0; nt < 16; nt++) {
        sc[nt][0] = exp2f((sc[nt][0] - m0) * LOG2E); s0 += sc[nt][0];
        sc[nt][1] = exp2f((sc[nt][1] - m0) * LOG2E); s0 += sc[nt][1];
        sc[nt][2] = exp2f((sc[nt][2] - m1) * LOG2E); s1 += sc[nt][2];
        sc[nt][3] = exp2f((sc[nt][3] - m1) * LOG2E); s1 += sc[nt][3];
    }
    s0 += __shfl_xor_sync(0xffffffffu, s0, 1);
    s0 += __shfl_xor_sync(0xffffffffu, s0, 2);
    s1 += __shfl_xor_sync(0xffffffffu, s1, 1);
    s1 += __shfl_xor_sync(0xffffffffu, s1, 2);
    const float inv0 = 1.0f / s0, inv1 = 1.0f / s1;

    // P half 1 (t cols 0..63) -> bufB
#pragma unroll
    for (int nt = 0; nt < 8; nt++) {
        int n = nt * 8 + 2 * qc;
        Ps[(row + g) * 68 + n] = tf32f(sc[nt][0] * inv0);
        Ps[(row + g) * 68 + n + 1] = tf32f(sc[nt][1] * inv0);
        Ps[(row + g + 8) * 68 + n] = tf32f(sc[nt][2] * inv1);
        Ps[(row + g + 8) * 68 + n + 1] = tf32f(sc[nt][3] * inv1);
    }
    CP_WAIT(0);                      // V landed
    __syncthreads();

    // ---- PV: warp = rows 16w..16w+15, all 64 d; two k-passes ----
    float oa[8][4];
#pragma unroll
    for (int j = 0; j < 8; j++)
#pragma unroll
        for (int k = 0; k < 4; k++) oa[j][k] = 0.f;

#pragma unroll
    for (int k0 = 0; k0 < 64; k0 += 8) {         // pass 1: t = 0..63
        uint32_t a[4];
        int rq = row + ((sub & 1) << 3) + rr;
        ldsm4(a, sb + BUFB_OFF + (uint32_t)(rq * 68 + k0 + ((sub >> 1) << 2)) * 4);
#pragma unroll
        for (int j = 0; j < 8; j++) {
            uint32_t bb[2];
            int n = j * 8 + g;
            bb[0] = fu(Vs[(k0 + qc) * 68 + n]);
            bb[1] = fu(Vs[(k0 + qc + 4) * 68 + n]);
            mma8(oa[j], a, bb);
        }
    }
    __syncthreads();
    // P half 2 (t cols 64..127) -> bufB
#pragma unroll
    for (int nt = 8; nt < 16; nt++) {
        int n = (nt - 8) * 8 + 2 * qc;
        Ps[(row + g) * 68 + n] = tf32f(sc[nt][0] * inv0);
        Ps[(row + g) * 68 + n + 1] = tf32f(sc[nt][1] * inv0);
        Ps[(row + g + 8) * 68 + n] = tf32f(sc[nt][2] * inv1);
        Ps[(row + g + 8) * 68 + n + 1] = tf32f(sc[nt][3] * inv1);
    }
    __syncthreads();
#pragma unroll
    for (int k0 = 0; k0 < 64; k0 += 8) {         // pass 2: t = 64..127
        uint32_t a[4];
        int rq = row + ((sub & 1) << 3) + rr;
        ldsm4(a, sb + BUFB_OFF + (uint32_t)(rq * 68 + k0 + ((sub >> 1) << 2)) * 4);
#pragma unroll
        for (int j = 0; j < 8; j++) {
            uint32_t bb[2];
            int n = j * 8 + g;
            bb[0] = fu(Vs[(64 + k0 + qc) * 68 + n]);
            bb[1] = fu(Vs[(64 + k0 + qc + 4) * 68 + n]);
            mma8(oa[j], a, bb);
        }
    }

    // direct STG: rows = s (16w+g, +8), cols = d
#pragma unroll
    for (int j = 0; j < 8; j++) {
        int r2 = row + g;
        int n = j * 8 + 2 * qc;
        *reinterpret_cast<float2*>(g_oc + base + (size_t)r2 * 8192 + (size_t)l * 64 + n) =
            make_float2(oa[j][0], oa[j][1]);
        *reinterpret_cast<float2*>(g_oc + base + (size_t)(r2 + 8) * 8192 + (size_t)l * 64 + n) =
            make_float2(oa[j][2], oa[j][3]);
    }
}

// K3: row attention + add col result + write final output [B,512,S,L].
__global__ void __launch_bounds__(256, 3) k_rowattn(float* __restrict__ out) {
    extern __shared__ float sm[];
    const uint32_t sb = smem_u32(sm);
    float* Vs = sm;
    float* Ps = sm + 128 * 68;
    const int tid = threadIdx.x;
    const int warp = tid >> 5, lane = tid & 31;
    const int g = lane >> 2, qc = lane & 3;
    const int sub = lane >> 3, rr = lane & 7;
    const int s = blockIdx.x, h = blockIdx.y, b = blockIdx.z;
    const size_t rbase = (size_t)((b * 8 + h) * 128) * 8192 + (size_t)s * 8192;

#pragma unroll
    for (int rep = 0; rep < 8; rep++) {
        int idx = rep * 256 + tid;
        int l = idx >> 4;
        int d4 = (idx & 15) * 4;
        size_t ga = rbase + (size_t)idx * 4;
        uint32_t so = (uint32_t)(l * 68 + d4) * 4;
        cpa16(sb + so, g_q + ga);
        cpa16(sb + BUFB_OFF + so, g_k + ga);
    }
    CP_COMMIT();
    CP_WAIT(0);
    __syncthreads();

    float sc[16][4];
#pragma unroll
    for (int nt = 0; nt < 16; nt++)
#pragma unroll
        for (int k = 0; k < 4; k++) sc[nt][k] = 0.f;
    const int row = warp * 16;
#pragma unroll
    for (int k0 = 0; k0 < 64; k0 += 8) {
        uint32_t a[4];
        {
            int rq = row + ((sub & 1) << 3) + rr;
            ldsm4(a, sb + (uint32_t)(rq * 68 + k0 + ((sub >> 1) << 2)) * 4);
        }
#pragma unroll
        for (int np = 0; np < 8; np++) {
            uint32_t bf[4];
            int n = np * 16 + ((sub >> 1) << 3) + rr;
            ldsm4(bf, sb + BUFB_OFF + (uint32_t)(n * 68 + k0 + ((sub & 1) << 2)) * 4);
            const uint32_t b0[2] = { bf[0], bf[1] };
            const uint32_t b1[2] = { bf[2], bf[3] };
            mma8(sc[np * 2], a, b0);
            mma8(sc[np * 2 + 1], a, b1);
        }
    }
    __syncthreads();

    // V -> bufA
#pragma unroll
    for (int rep = 0; rep < 8; rep++) {
        int idx = rep * 256 + tid;
        int l = idx >> 4;
        int d4 = (idx & 15) * 4;
        cpa16(sb + (uint32_t)(l * 68 + d4) * 4, g_v + rbase + (size_t)idx * 4);
    }
    CP_COMMIT();

    float m0 = -1e30f, m1 = -1e30f;
#pragma unroll
    for (int nt = 0; nt < 16; nt++) {
        m0 = fmaxf(m0, fmaxf(sc[nt][0], sc[nt][1]));
        m1 = fmaxf(m1, fmaxf(sc[nt][2], sc[nt][3]));
    }
    m0 = fmaxf(m0, __shfl_xor_sync(0xffffffffu, m0, 1));
    m0 = fmaxf(m0, __shfl_xor_sync(0xffffffffu, m0, 2));
    m1 = fmaxf(m1, __shfl_xor_sync(0xffffffffu, m1, 1));
    m1 = fmaxf(m1, __shfl_xor_sync(0xffffffffu, m1, 2));
    const float LOG2E = 1.4426950408889634f;
    float s0 = 0.f, s1 = 0.f;
#pragma unroll
    for (int nt = 0; nt < 16; nt++) {
        sc[nt][0] = exp2f((sc[nt][0] - m0) * LOG2E); s0 += sc[nt][0];
        sc[nt][1] = exp2f((sc[nt][1] - m0) * LOG2E); s0 += sc[nt][1];
        sc[nt][2] = exp2f((sc[nt][2] - m1) * LOG2E); s1 += sc[nt][2];
        sc[nt][3] = exp2f((sc[nt][3] - m1) * LOG2E); s1 += sc[nt][3];
    }
    s0 += __shfl_xor_sync(0xffffffffu, s0, 1);
    s0 += __shfl_xor_sync(0xffffffffu, s0, 2);
    s1 += __shfl_xor_sync(0xffffffffu, s1, 1);
    s1 += __shfl_xor_sync(0xffffffffu, s1, 2);
    const float inv0 = 1.0f / s0, inv1 = 1.0f / s1;

#pragma unroll
    for (int nt = 0; nt < 8; nt++) {
        int n = nt * 8 + 2 * qc;
        Ps[(row + g) * 68 + n] = tf32f(sc[nt][0] * inv0);
        Ps[(row + g) * 68 + n + 1] = tf32f(sc[nt][1] * inv0);
        Ps[(row + g + 8) * 68 + n] = tf32f(sc[nt][2] * inv1);
        Ps[(row + g + 8) * 68 + n + 1] = tf32f(sc[nt][3] * inv1);
    }
    CP_WAIT(0);
    __syncthreads();

    float oa[8][4];
#pragma unroll
    for (int j = 0; j < 8; j++)
#pragma unroll
        for (int k = 0; k < 4; k++) oa[j][k] = 0.f;

#pragma unroll
    for (int k0 = 0; k0 < 64; k0 += 8) {
        uint32_t a[4];
        int rq = row + ((sub & 1) << 3) + rr;
        ldsm4(a, sb + BUFB_OFF + (uint32_t)(rq * 68 + k0 + ((sub >> 1) << 2)) * 4);
#pragma unroll
        for (int j = 0; j < 8; j++) {
            uint32_t bb[2];
            int n = j * 8 + g;
            bb[0] = fu(Vs[(k0 + qc) * 68 + n]);
            bb[1] = fu(Vs[(k0 + qc + 4) * 68 + n]);
            mma8(oa[j], a, bb);
        }
    }
    __syncthreads();
#pragma unroll
    for (int nt = 8; nt < 16; nt++) {
        int n = (nt - 8) * 8 + 2 * qc;
        Ps[(row + g) * 68 + n] = tf32f(sc[nt][0] * inv0);
        Ps[(row + g) * 68 + n + 1] = tf32f(sc[nt][1] * inv0);
        Ps[(row + g + 8) * 68 + n] = tf32f(sc[nt][2] * inv1);
        Ps[(row + g + 8) * 68 + n + 1] = tf32f(sc[nt][3] * inv1);
    }
    __syncthreads();
#pragma unroll
    for (int k0 = 0; k0 < 64; k0 += 8) {
        uint32_t a[4];
        int rq = row + ((sub & 1) << 3) + rr;
        ldsm4(a, sb + BUFB_OFF + (uint32_t)(rq * 68 + k0 + ((sub >> 1) << 2)) * 4);
#pragma unroll
        for (int j = 0; j < 8; j++) {
            uint32_t bb[2];
            int n = j * 8 + g;
            bb[0] = fu(Vs[(64 + k0 + qc) * 68 + n]);
            bb[1] = fu(Vs[(64 + k0 + qc + 4) * 68 + n]);
            mma8(oa[j], a, bb);
        }
    }

    // fold col-attn result (rows = l, cols = d)
#pragma unroll
    for (int j = 0; j < 8; j++) {
        int lr = row + g;
        int n = j * 8 + 2 * qc;
        float2 c0 = *reinterpret_cast<const float2*>(g_oc + rbase + (size_t)lr * 64 + n);
        float2 c1 = *reinterpret_cast<const float2*>(g_oc + rbase + (size_t)(lr + 8) * 64 + n);
        oa[j][0] += c0.x;
        oa[j][1] += c0.y;
        oa[j][2] += c1.x;
        oa[j][3] += c1.y;
    }
    __syncthreads();                 // P reads done; Os overlays bufB
    float* Os = Ps;                  // [128][65]
#pragma unroll
    for (int j = 0; j < 8; j++) {
        int r2 = row + g;
        int n = j * 8 + 2 * qc;
        Os[r2 * 65 + n] = oa[j][0];
        Os[r2 * 65 + n + 1] = oa[j][1];
        Os[(r2 + 8) * 65 + n] = oa[j][2];
        Os[(r2 + 8) * 65 + n + 1] = oa[j][3];
    }
    __syncthreads();
    // transposed, fully coalesced final write: out[b][h*64+d][s][l]
#pragma unroll
    for (int rep = 0; rep < 8; rep++) {
        int idx = rep * 256 + tid;
        int d = idx >> 5;
        int l4 = (idx & 31) * 4;
        float4 v;
        v.x = Os[(l4 + 0) * 65 + d];
        v.y = Os[(l4 + 1) * 65 + d];
        v.z = Os[(l4 + 2) * 65 + d];
        v.w = Os[(l4 + 3) * 65 + d];
        size_t oaddr = (((size_t)(b * 512 + h * 64 + d)) * 128 + s) * 128 + l4;
        *reinterpret_cast<float4*>(out + oaddr) = v;
    }
}

extern "C" void kernel_launch(void* const* d_in, const int* in_sizes, int n_in,
                              void* d_out, int out_size) {
    const float* x = (const float*)d_in[0];
    const float* W = (const float*)d_in[1];
    const float* bias = (const float*)d_in[2];
    float* out = (float*)d_out;

    cudaFuncSetAttribute(k_xt, cudaFuncAttributeMaxDynamicSharedMemorySize, XT_SMEM);
    cudaFuncSetAttribute(k_qkv, cudaFuncAttributeMaxDynamicSharedMemorySize, K1_SMEM);
    cudaFuncSetAttribute(k_colattn, cudaFuncAttributeMaxDynamicSharedMemorySize, ATTN_SMEM);
    cudaFuncSetAttribute(k_rowattn, cudaFuncAttributeMaxDynamicSharedMemorySize, ATTN_SMEM);

    // X: transpose + round; W: round
    k_xt<<<dim3(128, 4, 2), 256, XT_SMEM>>>(x);
    {
        float* wr;  cudaGetSymbolAddress((void**)&wr, g_wr);
        int nw4 = 1536 * 512 / 4;            // 196,608
        k_round<<<(nw4 + 255) / 256, 256>>>(W, wr, nw4);
    }

    k_qkv<<<dim3(12, 128, 2), 256, K1_SMEM>>>(bias);
    k_colattn<<<dim3(128, 8, 2), 256, ATTN_SMEM>>>();
    k_rowattn<<<dim3(128, 8, 2), 256, ATTN_SMEM>>>(out);
}

// round 17
// speedup vs baseline: 1.0633x; 1.0570x over previous
#include <cuda_runtime.h>
#include <cstdint>

// Problem constants
// x: [B=2, E=512, S=128, L=128] fp32 ; W: [1536, 512] ; b: [1536]
// out: [2, 512, 128, 128] fp32
#define NB 2
#define NH 8
#define DH 64
#define NS 128
#define NL 128
#define QKV_ELEMS (NB * NH * NS * NL * DH)   // 16,777,216 floats = 64MB

__device__ __align__(256) float g_q[QKV_ELEMS];
__device__ __align__(256) float g_k[QKV_ELEMS];
__device__ __align__(256) float g_v[QKV_ELEMS];
__device__ __align__(256) float g_oc[QKV_ELEMS];
__device__ __align__(256) float g_xr[NB * 16384 * 512];   // X transposed [b][p][i], tf32-rounded
__device__ __align__(256) float g_wr[1536 * 512];         // tf32-rounded W

// ---------- helpers ----------
__device__ __forceinline__ uint32_t tf32u(float x) {
    uint32_t r;
    asm("cvt.rna.tf32.f32 %0, %1;" : "=r"(r) : "f"(x));
    return r;
}
__device__ __forceinline__ float tf32f(float x) { return __uint_as_float(tf32u(x)); }
__device__ __forceinline__ uint32_t fu(float x) { return __float_as_uint(x); }

__device__ __forceinline__ void mma8(float (&d)[4], const uint32_t (&a)[4], const uint32_t (&b)[2]) {
    asm volatile(
        "mma.sync.aligned.m16n8k8.row.col.f32.tf32.tf32.f32 "
        "{%0,%1,%2,%3}, {%4,%5,%6,%7}, {%8,%9}, {%0,%1,%2,%3};\n"
        : "+f"(d[0]), "+f"(d[1]), "+f"(d[2]), "+f"(d[3])
        : "r"(a[0]), "r"(a[1]), "r"(a[2]), "r"(a[3]), "r"(b[0]), "r"(b[1]));
}

// ldmatrix x4: lanes 8i..8i+7 supply the 16B-row addresses of matrix i.
__device__ __forceinline__ void ldsm4(uint32_t (&r)[4], uint32_t addr) {
    asm volatile("ldmatrix.sync.aligned.m8n8.x4.shared.b16 {%0,%1,%2,%3}, [%4];"
        : "=r"(r[0]), "=r"(r[1]), "=r"(r[2]), "=r"(r[3]) : "r"(addr));
}

__device__ __forceinline__ uint32_t smem_u32(const void* p) {
    uint32_t a;
    asm("{ .reg .u64 t; cvta.to.shared.u64 t, %1; cvt.u32.u64 %0, t; }" : "=r"(a) : "l"(p));
    return a;
}
__device__ __forceinline__ void cpa16(uint32_t dst, const void* src) {
    asm volatile("cp.async.cg.shared.global [%0], [%1], 16;" :: "r"(dst), "l"(src) : "memory");
}
#define CP_COMMIT() asm volatile("cp.async.commit_group;" ::: "memory")
#define CP_WAIT(n)  asm volatile("cp.async.wait_group %0;" :: "n"(n) : "memory")

// =====================================================================
// K0a: transpose X [b][i][p] -> g_xr [b][p][i], tf32-rounded. occ 3.
// =====================================================================
#define XT_SMEM (128 * 129 * 4)
__global__ void __launch_bounds__(256, 3) k_xt(const float* __restrict__ X) {
    extern __shared__ float sm[];
    float* t = sm;
    const int tid = threadIdx.x;
    const int p0 = blockIdx.x * 128, i0 = blockIdx.y * 128, b = blockIdx.z;
    const float* src = X + ((size_t)(b * 512 + i0)) * 16384 + p0;
#pragma unroll
    for (int it = 0; it < 16; it++) {
        int idx = it * 256 + tid;
        int i = idx >> 5, p4 = (idx & 31) * 4;
        float4 v = *reinterpret_cast<const float4*>(src + (size_t)i * 16384 + p4);
        t[i * 129 + p4 + 0] = tf32f(v.x);
        t[i * 129 + p4 + 1] = tf32f(v.y);
        t[i * 129 + p4 + 2] = tf32f(v.z);
        t[i * 129 + p4 + 3] = tf32f(v.w);
    }
    __syncthreads();
    float* dst = g_xr + ((size_t)(b * 16384 + p0)) * 512 + i0;
#pragma unroll
    for (int it = 0; it < 16; it++) {
        int idx = it * 256 + tid;
        int p = idx >> 5, i4 = (idx & 31) * 4;
        float4 v;
        v.x = t[(i4 + 0) * 129 + p];
        v.y = t[(i4 + 1) * 129 + p];
        v.z = t[(i4 + 2) * 129 + p];
        v.w = t[(i4 + 3) * 129 + p];
        *reinterpret_cast<float4*>(dst + (size_t)p * 512 + i4) = v;
    }
}

// K0b: tf32-round a buffer (for W).
__global__ void k_round(const float* __restrict__ src, float* __restrict__ dst, int n4) {
    int i = blockIdx.x * blockDim.x + threadIdx.x;
    if (i < n4) {
        float4 v = reinterpret_cast<const float4*>(src)[i];
        reinterpret_cast<float4*>(dst)[i] = make_float4(tf32f(v.x), tf32f(v.y), tf32f(v.z), tf32f(v.w));
    }
}

// =====================================================================
// K1: QKV GEMM (R14 config: 128x128 tile, occ 2, 3-stage cp.async).
// C[o, p] = sum_i Wr[o,i] * Xr[b][p,i] (+bias), p = s*128+l
// smem: A0/A1/A2 [0,49152), B0/B1/B2 [49152,98304). Cs [128][129] overlays.
// Outputs q,k,v written tf32-ROUNDED (post bias+scale).
// =====================================================================
#define K1_SMEM 98304

__global__ void __launch_bounds__(256, 2) k_qkv(const float* __restrict__ bias) {
    extern __shared__ float sm[];
    const uint32_t sb = smem_u32(sm);
    const int tid = threadIdx.x;
    const int warp = tid >> 5, lane = tid & 31;
    const int g = lane >> 2, qc = lane & 3;
    const int sub = lane >> 3, rr = lane & 7;       // ldmatrix lane decomposition
    const int wm = warp >> 2, wn = warp & 3;        // 2 x 4 warp grid
    const int o0 = blockIdx.x * 128;
    const int s = blockIdx.y;
    const int b = blockIdx.z;
    const float* Wt = g_wr + (size_t)o0 * 512;
    const float* Bt = g_xr + ((size_t)b * 16384 + (size_t)s * 128) * 512;

    float acc[4][4][4];
#pragma unroll
    for (int i = 0; i < 4; i++)
#pragma unroll
        for (int j = 0; j < 4; j++)
#pragma unroll
            for (int k = 0; k < 4; k++) acc[i][j][k] = 0.f;

    auto stage = [&](int c, int buf) {
        const float* wa = Wt + c * 32;
#pragma unroll
        for (int it = 0; it < 4; it++) {
            int idx = it * 256 + tid;
            int r = idx >> 3;
            int kq = idx & 7;
            uint32_t dst = sb + (uint32_t)(buf * 16384 + r * 128 + ((kq ^ (r & 7)) << 4));
            cpa16(dst, wa + (size_t)r * 512 + kq * 4);
        }
        const float* xa = Bt + c * 32;
#pragma unroll
        for (int it = 0; it < 4; it++) {
            int idx = it * 256 + tid;
            int r = idx >> 3;
            int kq = idx & 7;
            uint32_t dst = sb + (uint32_t)(49152 + buf * 16384 + r * 128 + ((kq ^ (r & 7)) << 4));
            cpa16(dst, xa + (size_t)r * 512 + kq * 4);
        }
    };

    auto compute = [&](int buf) {
        const uint32_t Ab = sb + (uint32_t)(buf * 16384);
        const uint32_t Bb = sb + (uint32_t)(49152 + buf * 16384);
#pragma unroll
        for (int s8 = 0; s8 < 4; s8++) {
            uint32_t af[4][4], bf[2][4];
#pragma unroll
            for (int mt = 0; mt < 4; mt++) {
                int row = wm * 64 + mt * 16 + ((sub & 1) << 3) + rr;
                int q = 2 * s8 + (sub >> 1);
                ldsm4(af[mt], Ab + (uint32_t)(row * 128 + ((q ^ (row & 7)) << 4)));
            }
#pragma unroll
            for (int np = 0; np < 2; np++) {
                int n = wn * 32 + np * 16 + ((sub >> 1) << 3) + rr;
                int q = 2 * s8 + (sub & 1);
                ldsm4(bf[np], Bb + (uint32_t)(n * 128 + ((q ^ (n & 7)) << 4)));
            }
#pragma unroll
            for (int mt = 0; mt < 4; mt++)
#pragma unroll
                for (int nt = 0; nt < 4; nt++) {
                    const uint32_t bb[2] = { bf[nt >> 1][(nt & 1) * 2], bf[nt >> 1][(nt & 1) * 2 + 1] };
                    mma8(acc[mt][nt], af[mt], bb);
                }
        }
    };

    stage(0, 0);
    CP_COMMIT();
    stage(1, 1);
    CP_COMMIT();
    for (int c = 0; c < 16; c++) {
        if (c < 15) { CP_WAIT(1); } else { CP_WAIT(0); }
        __syncthreads();
        compute(c % 3);
        if (c + 2 < 16) {
            stage(c + 2, (c + 2) % 3);
            CP_COMMIT();
        }
    }
    __syncthreads();

    float* Cs = sm;   // [128][129]
#pragma unroll
    for (int mt = 0; mt < 4; mt++)
#pragma unroll
        for (int nt = 0; nt < 4; nt++) {
            int r = wm * 64 + mt * 16 + g;
            int n = wn * 32 + nt * 8 + 2 * qc;
            Cs[r * 129 + n] = acc[mt][nt][0];
            Cs[r * 129 + n + 1] = acc[mt][nt][1];
            Cs[(r + 8) * 129 + n] = acc[mt][nt][2];
            Cs[(r + 8) * 129 + n + 1] = acc[mt][nt][3];
        }
    __syncthreads();

    const int sel = o0 >> 9;                 // 0=q 1=k 2=v
    const int h0 = (o0 & 511) >> 6;
    float* dst = (sel == 0) ? g_q : ((sel == 1) ? g_k : g_v);
    const float scale = (sel == 0) ? 0.125f : 1.0f;
#pragma unroll
    for (int rep = 0; rep < 16; rep++) {
        int idx = rep * 256 + tid;
        int d4 = (idx & 15) * 4;
        int l = (idx >> 4) & 127;
        int hh = idx >> 11;
        int od = hh * 64 + d4;
        float4 v;
        v.x = tf32f((Cs[(od + 0) * 129 + l] + bias[o0 + od + 0]) * scale);
        v.y = tf32f((Cs[(od + 1) * 129 + l] + bias[o0 + od + 1]) * scale);
        v.z = tf32f((Cs[(od + 2) * 129 + l] + bias[o0 + od + 2]) * scale);
        v.w = tf32f((Cs[(od + 3) * 129 + l] + bias[o0 + od + 3]) * scale);
        size_t da = (((size_t)((b * 8 + h0 + hh) * 128 + s)) * 128 + l) * 64 + d4;
        *reinterpret_cast<float4*>(dst + da) = v;
    }
}

// =====================================================================
// Attention core (R14 structure): 128 x 128 x 64 per CTA, 8 warps, 2 CTA/SM.
// Q+K in cp.async group 0, V in group 1 (QK starts before V lands).
// QK: warp = 16 rows (shuffle softmax), frags via ldmatrix.
// PV: warp grid 2m x 4n (64 rows x 16 cols) — halves V scalar-LDS redundancy.
// smem: Qs[128][68] | Ks[128][68] | Vs[128][68]; Ps[128][132] overlays Qs+Ks.
// =====================================================================
#define ATTN_SMEM (3 * 128 * 68 * 4)   // 104,448 B
#define QS_OFF 0
#define KS_OFF (128 * 68 * 4)
#define VS_OFF (2 * 128 * 68 * 4)

// K2: column attention. Block = (l, h, b). Writes g_oc[b][h][s][l][d].
__global__ void __launch_bounds__(256, 2) k_colattn() {
    extern __shared__ float sm[];
    const uint32_t sb = smem_u32(sm);
    float* Vs = sm + 2 * 128 * 68;
    float* Ps = sm;                   // [128][132] overlay on Qs+Ks
    const int tid = threadIdx.x;
    const int warp = tid >> 5, lane = tid & 31;
    const int g = lane >> 2, qc = lane & 3;
    const int sub = lane >> 3, rr = lane & 7;
    const int l = blockIdx.x, h = blockIdx.y, b = blockIdx.z;
    const size_t base = (size_t)((b * 8 + h) * 128) * 8192;

    // group 0: Q + K; group 1: V
#pragma unroll
    for (int rep = 0; rep < 8; rep++) {
        int idx = rep * 256 + tid;
        int s = idx >> 4;
        int d4 = (idx & 15) * 4;
        size_t ga = base + (size_t)s * 8192 + (size_t)l * 64 + d4;
        uint32_t so = (uint32_t)(s * 68 + d4) * 4;
        cpa16(sb + QS_OFF + so, g_q + ga);
        cpa16(sb + KS_OFF + so, g_k + ga);
    }
    CP_COMMIT();
#pragma unroll
    for (int rep = 0; rep < 8; rep++) {
        int idx = rep * 256 + tid;
        int s = idx >> 4;
        int d4 = (idx & 15) * 4;
        size_t ga = base + (size_t)s * 8192 + (size_t)l * 64 + d4;
        cpa16(sb + VS_OFF + (uint32_t)(s * 68 + d4) * 4, g_v + ga);
    }
    CP_COMMIT();
    CP_WAIT(1);            // Q,K ready; V still in flight
    __syncthreads();

    // ---- QK: scores[s][t], warp owns rows 16w..16w+15 ----
    float sc[16][4];
#pragma unroll
    for (int nt = 0; nt < 16; nt++)
#pragma unroll
        for (int k = 0; k < 4; k++) sc[nt][k] = 0.f;
    const int row = warp * 16;
#pragma unroll
    for (int k0 = 0; k0 < 64; k0 += 8) {
        uint32_t a[4];
        {
            int rq = row + ((sub & 1) << 3) + rr;
            ldsm4(a, sb + QS_OFF + (uint32_t)(rq * 68 + k0 + ((sub >> 1) << 2)) * 4);
        }
#pragma unroll
        for (int np = 0; np < 8; np++) {
            uint32_t bf[4];
            int n = np * 16 + ((sub >> 1) << 3) + rr;
            ldsm4(bf, sb + KS_OFF + (uint32_t)(n * 68 + k0 + ((sub & 1) << 2)) * 4);
            const uint32_t b0[2] = { bf[0], bf[1] };
            const uint32_t b1[2] = { bf[2], bf[3] };
            mma8(sc[np * 2], a, b0);
            mma8(sc[np * 2 + 1], a, b1);
        }
    }
    // ---- softmax over t ----
    float m0 = -1e30f, m1 = -1e30f;
#pragma unroll
    for (int nt = 0; nt < 16; nt++) {
        m0 = fmaxf(m0, fmaxf(sc[nt][0], sc[nt][1]));
        m1 = fmaxf(m1, fmaxf(sc[nt][2], sc[nt][3]));
    }
    m0 = fmaxf(m0, __shfl_xor_sync(0xffffffffu, m0, 1));
    m0 = fmaxf(m0, __shfl_xor_sync(0xffffffffu, m0, 2));
    m1 = fmaxf(m1, __shfl_xor_sync(0xffffffffu, m1, 1));
    m1 = fmaxf(m1, __shfl_xor_sync(0xffffffffu, m1, 2));
    const float LOG2E = 1.4426950408889634f;
    float s0 = 0.f, s1 = 0.f;
#pragma unroll
    for (int nt = 0; nt < 16; nt++) {
        sc[nt][0] = exp2f((sc[nt][0] - m0) * LOG2E); s0 += sc[nt][0];
        sc[nt][1] = exp2f((sc[nt][1] - m0) * LOG2E); s0 += sc[nt][1];
        sc[nt][2] = exp2f((sc[nt][2] - m1) * LOG2E); s1 += sc[nt][2];
        sc[nt][3] = exp2f((sc[nt][3] - m1) * LOG2E); s1 += sc[nt][3];
    }
    s0 += __shfl_xor_sync(0xffffffffu, s0, 1);
    s0 += __shfl_xor_sync(0xffffffffu, s0, 2);
    s1 += __shfl_xor_sync(0xffffffffu, s1, 1);
    s1 += __shfl_xor_sync(0xffffffffu, s1, 2);
    const float inv0 = 1.0f / s0, inv1 = 1.0f / s1;

    __syncthreads();                         // Qs/Ks dead; Ps may overwrite
#pragma unroll
    for (int nt = 0; nt < 16; nt++) {
        int n = nt * 8 + 2 * qc;
        Ps[(row + g) * 132 + n] = tf32f(sc[nt][0] * inv0);
        Ps[(row + g) * 132 + n + 1] = tf32f(sc[nt][1] * inv0);
        Ps[(row + g + 8) * 132 + n] = tf32f(sc[nt][2] * inv1);
        Ps[(row + g + 8) * 132 + n + 1] = tf32f(sc[nt][3] * inv1);
    }
    CP_WAIT(0);                              // V landed long ago
    __syncthreads();

    // ---- PV: warp grid 2m x 4n (64 rows x 16 cols per warp) ----
    const int wm3 = warp >> 2, wn3 = warp & 3;
    float oa[4][2][4];
#pragma unroll
    for (int mt = 0; mt < 4; mt++)
#pragma unroll
        for (int nt = 0; nt < 2; nt++)
#pragma unroll
            for (int k = 0; k < 4; k++) oa[mt][nt][k] = 0.f;
#pragma unroll
    for (int k0 = 0; k0 < 128; k0 += 8) {
        uint32_t a[4][4];
#pragma unroll
        for (int mt = 0; mt < 4; mt++) {
            int rp = wm3 * 64 + mt * 16 + ((sub & 1) << 3) + rr;
            ldsm4(a[mt], sb + QS_OFF + (uint32_t)(rp * 132 + k0 + ((sub >> 1) << 2)) * 4);
        }
#pragma unroll
        for (int nt = 0; nt < 2; nt++) {
            uint32_t bb[2];
            int n = wn3 * 16 + nt * 8 + g;
            bb[0] = fu(Vs[(k0 + qc) * 68 + n]);
            bb[1] = fu(Vs[(k0 + qc + 4) * 68 + n]);
#pragma unroll
            for (int mt = 0; mt < 4; mt++) mma8(oa[mt][nt], a[mt], bb);
        }
    }
    // direct STG from accumulators: rows = s, cols = d
#pragma unroll
    for (int mt = 0; mt < 4; mt++)
#pragma unroll
        for (int nt = 0; nt < 2; nt++) {
            int r2 = wm3 * 64 + mt * 16 + g;
            int n = wn3 * 16 + nt * 8 + 2 * qc;
            *reinterpret_cast<float2*>(g_oc + base + (size_t)r2 * 8192 + (size_t)l * 64 + n) =
                make_float2(oa[mt][nt][0], oa[mt][nt][1]);
            *reinterpret_cast<float2*>(g_oc + base + (size_t)(r2 + 8) * 8192 + (size_t)l * 64 + n) =
                make_float2(oa[mt][nt][2], oa[mt][nt][3]);
        }
}

// K3: row attention + add col result + write final output [B,512,S,L].
__global__ void __launch_bounds__(256, 2) k_rowattn(float* __restrict__ out) {
    extern __shared__ float sm[];
    const uint32_t sb = smem_u32(sm);
    float* Vs = sm + 2 * 128 * 68;
    float* Ps = sm;                  // [128][132] overlay on Qs+Ks
    float* Os = sm;                  // [128][65] overlay
    const int tid = threadIdx.x;
    const int warp = tid >> 5, lane = tid & 31;
    const int g = lane >> 2, qc = lane & 3;
    const int sub = lane >> 3, rr = lane & 7;
    const int s = blockIdx.x, h = blockIdx.y, b = blockIdx.z;
    const size_t rbase = (size_t)((b * 8 + h) * 128) * 8192 + (size_t)s * 8192;

#pragma unroll
    for (int rep = 0; rep < 8; rep++) {
        int idx = rep * 256 + tid;
        int l = idx >> 4;
        int d4 = (idx & 15) * 4;
        size_t ga = rbase + (size_t)idx * 4;
        uint32_t so = (uint32_t)(l * 68 + d4) * 4;
        cpa16(sb + QS_OFF + so, g_q + ga);
        cpa16(sb + KS_OFF + so, g_k + ga);
    }
    CP_COMMIT();
#pragma unroll
    for (int rep = 0; rep < 8; rep++) {
        int idx = rep * 256 + tid;
        int l = idx >> 4;
        int d4 = (idx & 15) * 4;
        cpa16(sb + VS_OFF + (uint32_t)(l * 68 + d4) * 4, g_v + rbase + (size_t)idx * 4);
    }
    CP_COMMIT();
    CP_WAIT(1);
    __syncthreads();

    float sc[16][4];
#pragma unroll
    for (int nt = 0; nt < 16; nt++)
#pragma unroll
        for (int k = 0; k < 4; k++) sc[nt][k] = 0.f;
    const int row = warp * 16;
#pragma unroll
    for (int k0 = 0; k0 < 64; k0 += 8) {
        uint32_t a[4];
        {
            int rq = row + ((sub & 1) << 3) + rr;
            ldsm4(a, sb + QS_OFF + (uint32_t)(rq * 68 + k0 + ((sub >> 1) << 2)) * 4);
        }
#pragma unroll
        for (int np = 0; np < 8; np++) {
            uint32_t bf[4];
            int n = np * 16 + ((sub >> 1) << 3) + rr;
            ldsm4(bf, sb + KS_OFF + (uint32_t)(n * 68 + k0 + ((sub & 1) << 2)) * 4);
            const uint32_t b0[2] = { bf[0], bf[1] };
            const uint32_t b1[2] = { bf[2], bf[3] };
            mma8(sc[np * 2], a, b0);
            mma8(sc[np * 2 + 1], a, b1);
        }
    }
    float m0 = -1e30f, m1 = -1e30f;
#pragma unroll
    for (int nt = 0; nt < 16; nt++) {
        m0 = fmaxf(m0, fmaxf(sc[nt][0], sc[nt][1]));
        m1 = fmaxf(m1, fmaxf(sc[nt][2], sc[nt][3]));
    }
    m0 = fmaxf(m0, __shfl_xor_sync(0xffffffffu, m0, 1));
    m0 = fmaxf(m0, __shfl_xor_sync(0xffffffffu, m0, 2));
    m1 = fmaxf(m1, __shfl_xor_sync(0xffffffffu, m1, 1));
    m1 = fmaxf(m1, __shfl_xor_sync(0xffffffffu, m1, 2));
    const float LOG2E = 1.4426950408889634f;
    float s0 = 0.f, s1 = 0.f;
#pragma unroll
    for (int nt = 0; nt < 16; nt++) {
        sc[nt][0] = exp2f((sc[nt][0] - m0) * LOG2E); s0 += sc[nt][0];
        sc[nt][1] = exp2f((sc[nt][1] - m0) * LOG2E); s0 += sc[nt][1];
        sc[nt][2] = exp2f((sc[nt][2] - m1) * LOG2E); s1 += sc[nt][2];
        sc[nt][3] = exp2f((sc[nt][3] - m1) * LOG2E); s1 += sc[nt][3];
    }
    s0 += __shfl_xor_sync(0xffffffffu, s0, 1);
    s0 += __shfl_xor_sync(0xffffffffu, s0, 2);
    s1 += __shfl_xor_sync(0xffffffffu, s1, 1);
    s1 += __shfl_xor_sync(0xffffffffu, s1, 2);
    const float inv0 = 1.0f / s0, inv1 = 1.0f / s1;

    __syncthreads();
#pragma unroll
    for (int nt = 0; nt < 16; nt++) {
        int n = nt * 8 + 2 * qc;
        Ps[(row + g) * 132 + n] = tf32f(sc[nt][0] * inv0);
        Ps[(row + g) * 132 + n + 1] = tf32f(sc[nt][1] * inv0);
        Ps[(row + g + 8) * 132 + n] = tf32f(sc[nt][2] * inv1);
        Ps[(row + g + 8) * 132 + n + 1] = tf32f(sc[nt][3] * inv1);
    }
    CP_WAIT(0);
    __syncthreads();

    // ---- PV: warp grid 2m x 4n ----
    const int wm3 = warp >> 2, wn3 = warp & 3;
    float oa[4][2][4];
#pragma unroll
    for (int mt = 0; mt < 4; mt++)
#pragma unroll
        for (int nt = 0; nt < 2; nt++)
#pragma unroll
            for (int k = 0; k < 4; k++) oa[mt][nt][k] = 0.f;
#pragma unroll
    for (int k0 = 0; k0 < 128; k0 += 8) {
        uint32_t a[4][4];
#pragma unroll
        for (int mt = 0; mt < 4; mt++) {
            int rp = wm3 * 64 + mt * 16 + ((sub & 1) << 3) + rr;
            ldsm4(a[mt], sb + QS_OFF + (uint32_t)(rp * 132 + k0 + ((sub >> 1) << 2)) * 4);
        }
#pragma unroll
        for (int nt = 0; nt < 2; nt++) {
            uint32_t bb[2];
            int n = wn3 * 16 + nt * 8 + g;
            bb[0] = fu(Vs[(k0 + qc) * 68 + n]);
            bb[1] = fu(Vs[(k0 + qc + 4) * 68 + n]);
#pragma unroll
            for (int mt = 0; mt < 4; mt++) mma8(oa[mt][nt], a[mt], bb);
        }
    }
    // fold col-attn result into accumulators (rows = l, cols = d)
#pragma unroll
    for (int mt = 0; mt < 4; mt++)
#pragma unroll
        for (int nt = 0; nt < 2; nt++) {
            int lr = wm3 * 64 + mt * 16 + g;
            int n = wn3 * 16 + nt * 8 + 2 * qc;
            float2 c0 = *reinterpret_cast<const float2*>(g_oc + rbase + (size_t)lr * 64 + n);
            float2 c1 = *reinterpret_cast<const float2*>(g_oc + rbase + (size_t)(lr + 8) * 64 + n);
            oa[mt][nt][0] += c0.x;
            oa[mt][nt][1] += c0.y;
            oa[mt][nt][2] += c1.x;
            oa[mt][nt][3] += c1.y;
        }
    __syncthreads();                 // all warps done reading Ps before Os overlay
#pragma unroll
    for (int mt = 0; mt < 4; mt++)
#pragma unroll
        for (int nt = 0; nt < 2; nt++) {
            int r2 = wm3 * 64 + mt * 16 + g;
            int n = wn3 * 16 + nt * 8 + 2 * qc;
            Os[r2 * 65 + n] = oa[mt][nt][0];
            Os[r2 * 65 + n + 1] = oa[mt][nt][1];
            Os[(r2 + 8) * 65 + n] = oa[mt][nt][2];
            Os[(r2 + 8) * 65 + n + 1] = oa[mt][nt][3];
        }
    __syncthreads();
    // transposed, fully coalesced final write: out[b][h*64+d][s][l]
#pragma unroll
    for (int rep = 0; rep < 8; rep++) {
        int idx = rep * 256 + tid;
        int d = idx >> 5;
        int l4 = (idx & 31) * 4;
        float4 v;
        v.x = Os[(l4 + 0) * 65 + d];
        v.y = Os[(l4 + 1) * 65 + d];
        v.z = Os[(l4 + 2) * 65 + d];
        v.w = Os[(l4 + 3) * 65 + d];
        size_t oaddr = (((size_t)(b * 512 + h * 64 + d)) * 128 + s) * 128 + l4;
        *reinterpret_cast<float4*>(out + oaddr) = v;
    }
}

extern "C" void kernel_launch(void* const* d_in, const int* in_sizes, int n_in,
                              void* d_out, int out_size) {
    const float* x = (const float*)d_in[0];
    const float* W = (const float*)d_in[1];
    const float* bias = (const float*)d_in[2];
    float* out = (float*)d_out;

    cudaFuncSetAttribute(k_xt, cudaFuncAttributeMaxDynamicSharedMemorySize, XT_SMEM);
    cudaFuncSetAttribute(k_qkv, cudaFuncAttributeMaxDynamicSharedMemorySize, K1_SMEM);
    cudaFuncSetAttribute(k_colattn, cudaFuncAttributeMaxDynamicSharedMemorySize, ATTN_SMEM);
    cudaFuncSetAttribute(k_rowattn, cudaFuncAttributeMaxDynamicSharedMemorySize, ATTN_SMEM);

    // X: transpose + round; W: round
    k_xt<<<dim3(128, 4, 2), 256, XT_SMEM>>>(x);
    {
        float* wr;  cudaGetSymbolAddress((void**)&wr, g_wr);
        int nw4 = 1536 * 512 / 4;            // 196,608
        k_round<<<(nw4 + 255) / 256, 256>>>(W, wr, nw4);
    }

    k_qkv<<<dim3(12, 128, 2), 256, K1_SMEM>>>(bias);
    k_colattn<<<dim3(128, 8, 2), 256, ATTN_SMEM>>>();
    k_rowattn<<<dim3(128, 8, 2), 256, ATTN_SMEM>>>(out);
}